// round 8
// baseline (speedup 1.0000x reference)
#include <cuda_runtime.h>
#include <cuda_fp16.h>
#include <cstdint>

#define D_IN   2048
#define D_OUT  2048
#define M_TOK  8192
#define RANK   16
#define NEXP   8
#define SCALING 1.0f

// fp16 operands, precomputed. 40MB total, static device globals.
__device__ __half g_Xh[(size_t)M_TOK * D_IN];
__device__ __half g_Wh[(size_t)D_OUT * D_IN];

// ---------------------------------------------------------------------------
// helpers
// ---------------------------------------------------------------------------
__device__ __forceinline__ uint32_t smem_u32(const void* p) {
    uint32_t a;
    asm("{ .reg .u64 t; cvta.to.shared.u64 t, %1; cvt.u32.u64 %0, t; }" : "=r"(a) : "l"(p));
    return a;
}
__device__ __forceinline__ void cpa16(uint32_t s, const void* g) {
    asm volatile("cp.async.cg.shared.global [%0], [%1], 16;" :: "r"(s), "l"(g));
}
__device__ __forceinline__ void cpa_commit() {
    asm volatile("cp.async.commit_group;" ::: "memory");
}
template <int N> __device__ __forceinline__ void cpa_wait() {
    asm volatile("cp.async.wait_group %0;" :: "n"(N) : "memory");
}
__device__ __forceinline__ void ldsm_x4(uint32_t addr, uint32_t& r0, uint32_t& r1,
                                        uint32_t& r2, uint32_t& r3) {
    asm volatile("ldmatrix.sync.aligned.m8n8.x4.shared.b16 {%0,%1,%2,%3}, [%4];"
                 : "=r"(r0), "=r"(r1), "=r"(r2), "=r"(r3) : "r"(addr));
}
__device__ __forceinline__ void mma_fp16(float& c0, float& c1, float& c2, float& c3,
                                         uint32_t a0, uint32_t a1, uint32_t a2, uint32_t a3,
                                         uint32_t b0, uint32_t b1) {
    asm volatile(
        "mma.sync.aligned.m16n8k16.row.col.f32.f16.f16.f32 "
        "{%0,%1,%2,%3}, {%4,%5,%6,%7}, {%8,%9}, {%0,%1,%2,%3};"
        : "+f"(c0), "+f"(c1), "+f"(c2), "+f"(c3)
        : "r"(a0), "r"(a1), "r"(a2), "r"(a3), "r"(b0), "r"(b1));
}
__device__ __forceinline__ uint2 pack_h4(float4 v) {
    __half2 p0 = __floats2half2_rn(v.x, v.y);
    __half2 p1 = __floats2half2_rn(v.z, v.w);
    uint2 u;
    u.x = *(uint32_t*)&p0;
    u.y = *(uint32_t*)&p1;
    return u;
}

// ---------------------------------------------------------------------------
// Kernel 0: convert x to fp16
// ---------------------------------------------------------------------------
__global__ __launch_bounds__(256) void convert_x_kernel(const float* __restrict__ x)
{
    size_t i4 = (size_t)blockIdx.x * 256 + threadIdx.x;   // float4 index
    float4 v = __ldg((const float4*)x + i4);
    *(uint2*)&g_Xh[i4 * 4] = pack_h4(v);
}

// ---------------------------------------------------------------------------
// Kernel 1: fold LoRA into W, output fp16. 128x128 tile (proven fastest).
// ---------------------------------------------------------------------------
__global__ __launch_bounds__(256) void fold_kernel(
    const float* __restrict__ W,
    const float* __restrict__ A,          // lora_A as [128, D_IN]
    const float* __restrict__ Bl,         // [E, D_OUT, R]
    const int* __restrict__ mask)
{
    __shared__ __align__(16) float sB[16][132];
    __shared__ __align__(16) float sA[16][132];

    const int t  = threadIdx.x;
    const int tr = t >> 4;
    const int tc = t & 15;
    const int o0 = blockIdx.y * 128;
    const int d0 = blockIdx.x * 128;

    float acc[8][8];
#pragma unroll
    for (int i = 0; i < 8; ++i)
#pragma unroll
        for (int j = 0; j < 8; ++j) acc[i][j] = 0.f;

    for (int c = 0; c < NEXP; ++c) {
        const float sc = (mask[c] != 0) ? SCALING : 0.f;
#pragma unroll
        for (int i = 0; i < 8; ++i) {
            int idx = t + i * 256;
            int ol = idx >> 4, r = idx & 15;
            sB[r][ol] = Bl[(size_t)c * D_OUT * RANK + (size_t)(o0 + ol) * RANK + r] * sc;
        }
#pragma unroll
        for (int i = 0; i < 8; ++i) {
            int idx = t + i * 256;
            int kk = idx >> 7, dl = idx & 127;
            sA[kk][dl] = A[(size_t)(c * 16 + kk) * D_IN + d0 + dl];
        }
        __syncthreads();
#pragma unroll
        for (int kk = 0; kk < 16; ++kk) {
            float4 b0 = *(const float4*)&sB[kk][tr * 8];
            float4 b1 = *(const float4*)&sB[kk][tr * 8 + 4];
            float4 a0 = *(const float4*)&sA[kk][tc * 8];
            float4 a1 = *(const float4*)&sA[kk][tc * 8 + 4];
            float ov[8] = {b0.x, b0.y, b0.z, b0.w, b1.x, b1.y, b1.z, b1.w};
            float dv[8] = {a0.x, a0.y, a0.z, a0.w, a1.x, a1.y, a1.z, a1.w};
#pragma unroll
            for (int i = 0; i < 8; ++i)
#pragma unroll
                for (int j = 0; j < 8; ++j) acc[i][j] += ov[i] * dv[j];
        }
        __syncthreads();
    }

#pragma unroll
    for (int i = 0; i < 8; ++i) {
        int o = o0 + tr * 8 + i;
#pragma unroll
        for (int j = 0; j < 8; j += 4) {
            int d = d0 + tc * 8 + j;
            float4 w = *(const float4*)&W[(size_t)o * D_IN + d];
            float4 r;
            r.x = w.x + acc[i][j + 0]; r.y = w.y + acc[i][j + 1];
            r.z = w.z + acc[i][j + 2]; r.w = w.w + acc[i][j + 3];
            *(uint2*)&g_Wh[(size_t)o * D_IN + d] = pack_h4(r);
        }
    }
}

// ---------------------------------------------------------------------------
// Kernel 2: fp16 GEMM via mma.sync.m16n8k16 (fp32 accumulate).
//   out[m,n] = sum_k x[m,k]*Weff[n,k] + bias[n]
// BM=128 BN=256 BK=64, 256 threads = 8 warps (2m x 4n), warp tile 64x64.
// 4-stage cp.async pipeline, ONE __syncthreads per K-iter.
// Rows are 128B; swizzle: seg' = seg ^ (row&7) -> conflict-free ldmatrix.
// ---------------------------------------------------------------------------
#define BK 64
#define NKT (D_IN / BK)            // 32
#define TILE_X_B 16384             // X tile: 128 rows x 128B
#define TILE_W_B 32768             // W tile: 256 rows x 128B
#define STG_B  (TILE_X_B + TILE_W_B)   // 48KB per stage
#define NSTG   4
#define SMEM_B (NSTG * STG_B)      // 192KB

__global__ __launch_bounds__(256, 1)
void gemm_mma_kernel(const float* __restrict__ bias, float* __restrict__ out)
{
    extern __shared__ __align__(1024) char smem[];
    const uint32_t sb = smem_u32(smem);

    const int t    = threadIdx.x;
    const int lane = t & 31;
    const int wid  = t >> 5;
    const int wm0  = (wid >> 2) * 64;     // warp m offset in tile (0/64)
    const int wn0  = (wid & 3) * 64;      // warp n offset in tile (0..192)
    const int n0   = blockIdx.x * 256;
    const int m0   = blockIdx.y * 128;

    // ldmatrix lane geometry
    const int a_row = wm0 + (lane & 7) + ((lane >> 3) & 1) * 8;  // + mi*16
    const int a_ks  = (lane >> 4);                               // + 2*j
    const int b_row = wn0 + (lane & 7) + (lane >> 4) * 8;        // + ni2*16
    const int b_ks  = (lane >> 3) & 1;                           // + 2*j
    const int a_r7  = a_row & 7;
    const int b_r7  = b_row & 7;

    float acc[4][8][4];
#pragma unroll
    for (int i = 0; i < 4; ++i)
#pragma unroll
        for (int j = 0; j < 8; ++j)
#pragma unroll
            for (int q = 0; q < 4; ++q) acc[i][j][q] = 0.f;

    // cp.async: X tile 1024 chunks (4/thread), W tile 2048 chunks (8/thread).
    auto issue_stage = [&](int kt, int stg) {
        const uint32_t base = sb + stg * STG_B;
        const int kbase = kt * BK;
#pragma unroll
        for (int ii = 0; ii < 4; ++ii) {
            int c = t + ii * 256;
            int row = c >> 3, seg = c & 7;
            uint32_t soff = (uint32_t)(row * 128 + ((seg ^ (row & 7)) << 4));
            cpa16(base + soff,
                  &g_Xh[(size_t)(m0 + row) * D_IN + kbase + seg * 8]);
        }
#pragma unroll
        for (int ii = 0; ii < 8; ++ii) {
            int c = t + ii * 256;
            int row = c >> 3, seg = c & 7;
            uint32_t soff = (uint32_t)(row * 128 + ((seg ^ (row & 7)) << 4));
            cpa16(base + TILE_X_B + soff,
                  &g_Wh[(size_t)(n0 + row) * D_IN + kbase + seg * 8]);
        }
        cpa_commit();
    };

    issue_stage(0, 0);
    issue_stage(1, 1);
    issue_stage(2, 2);

    for (int kt = 0; kt < NKT; ++kt) {
        // stage kt must be complete; outstanding groups: kt..min(kt+2, NKT-1)
        if (kt < NKT - 2)      cpa_wait<2>();
        else if (kt == NKT - 2) cpa_wait<1>();
        else                    cpa_wait<0>();
        __syncthreads();    // all warps done with stage (kt-1); safe to refill

        if (kt + 3 < NKT) issue_stage(kt + 3, (kt + 3) & 3);

        const uint32_t xh = sb + (kt & 3) * STG_B;
        const uint32_t wh = xh + TILE_X_B;

#pragma unroll
        for (int j = 0; j < 4; ++j) {               // k16 steps within BK=64
            uint32_t ah[4][4];
            const int aks = 2 * j + a_ks;
            const uint32_t axoff = (uint32_t)((aks ^ a_r7) << 4);
#pragma unroll
            for (int mi = 0; mi < 4; ++mi) {
                const uint32_t ro = (uint32_t)((a_row + mi * 16) * 128) + axoff;
                ldsm_x4(xh + ro, ah[mi][0], ah[mi][1], ah[mi][2], ah[mi][3]);
            }
            uint32_t bh[4][4];
            const int bks = 2 * j + b_ks;
            const uint32_t bxoff = (uint32_t)((bks ^ b_r7) << 4);
#pragma unroll
            for (int ni2 = 0; ni2 < 4; ++ni2) {
                const uint32_t ro = (uint32_t)((b_row + ni2 * 16) * 128) + bxoff;
                ldsm_x4(wh + ro, bh[ni2][0], bh[ni2][1], bh[ni2][2], bh[ni2][3]);
            }
#pragma unroll
            for (int mi = 0; mi < 4; ++mi) {
#pragma unroll
                for (int ni = 0; ni < 8; ++ni) {
                    const int g = ni >> 1, o = (ni & 1) * 2;
                    float* c = acc[mi][ni];
                    mma_fp16(c[0], c[1], c[2], c[3],
                             ah[mi][0], ah[mi][1], ah[mi][2], ah[mi][3],
                             bh[g][o], bh[g][o + 1]);
                }
            }
        }
    }

    // Epilogue: c layout m16n8: c0,c1 at (row=lane>>2, col=(lane&3)*2), c2,c3 at row+8.
    const int erow = lane >> 2;
    const int ecol = (lane & 3) * 2;
#pragma unroll
    for (int ni = 0; ni < 8; ++ni) {
        const int ncol = n0 + wn0 + ni * 8 + ecol;
        const float b0 = __ldg(&bias[ncol]);
        const float b1 = __ldg(&bias[ncol + 1]);
#pragma unroll
        for (int mi = 0; mi < 4; ++mi) {
            const int r0 = m0 + wm0 + mi * 16 + erow;
            float2 v0 = { acc[mi][ni][0] + b0, acc[mi][ni][1] + b1 };
            float2 v1 = { acc[mi][ni][2] + b0, acc[mi][ni][3] + b1 };
            *(float2*)&out[(size_t)r0 * D_OUT + ncol] = v0;
            *(float2*)&out[(size_t)(r0 + 8) * D_OUT + ncol] = v1;
        }
    }
}

// ---------------------------------------------------------------------------
// Inputs (metadata order): x, W, b, lora_A, lora_B, expert_mask
// ---------------------------------------------------------------------------
extern "C" void kernel_launch(void* const* d_in, const int* in_sizes, int n_in,
                              void* d_out, int out_size)
{
    const float* x    = (const float*)d_in[0];
    const float* W    = (const float*)d_in[1];
    const float* b    = (const float*)d_in[2];
    const float* lA   = (const float*)d_in[3];
    const float* lB   = (const float*)d_in[4];
    const int*   mask = (const int*)d_in[5];
    float* out = (float*)d_out;

    static bool attr_done = false;
    if (!attr_done) {
        cudaFuncSetAttribute(gemm_mma_kernel,
                             cudaFuncAttributeMaxDynamicSharedMemorySize, SMEM_B);
        attr_done = true;
    }

    dim3 blk(256);
    convert_x_kernel<<<(M_TOK * D_IN / 4) / 256, blk>>>(x);
    dim3 grid_fold(D_IN / 128, D_OUT / 128);    // (16, 16) = 256 blocks
    fold_kernel<<<grid_fold, blk>>>(W, lA, lB, mask);
    dim3 grid_gemm(D_OUT / 256, M_TOK / 128);   // (8, 64) = 512 CTAs
    gemm_mma_kernel<<<grid_gemm, blk, SMEM_B>>>(b, out);
}

// round 9
// speedup vs baseline: 1.1733x; 1.1733x over previous
#include <cuda_runtime.h>
#include <cuda_fp16.h>
#include <cstdint>

#define D_IN   2048
#define D_OUT  2048
#define M_TOK  8192
#define RANK   16
#define NEXP   8
#define SCALING 1.0f

// fp16 operands, precomputed. 40MB total, static device globals.
__device__ __half g_Xh[(size_t)M_TOK * D_IN];
__device__ __half g_Wh[(size_t)D_OUT * D_IN];

// ---------------------------------------------------------------------------
// helpers
// ---------------------------------------------------------------------------
__device__ __forceinline__ uint32_t smem_u32(const void* p) {
    uint32_t a;
    asm("{ .reg .u64 t; cvta.to.shared.u64 t, %1; cvt.u32.u64 %0, t; }" : "=r"(a) : "l"(p));
    return a;
}
__device__ __forceinline__ void cpa16(uint32_t s, const void* g) {
    asm volatile("cp.async.cg.shared.global [%0], [%1], 16;" :: "r"(s), "l"(g));
}
__device__ __forceinline__ void cpa_commit() {
    asm volatile("cp.async.commit_group;" ::: "memory");
}
template <int N> __device__ __forceinline__ void cpa_wait() {
    asm volatile("cp.async.wait_group %0;" :: "n"(N) : "memory");
}
__device__ __forceinline__ void ldsm_x4(uint32_t addr, uint32_t& r0, uint32_t& r1,
                                        uint32_t& r2, uint32_t& r3) {
    asm volatile("ldmatrix.sync.aligned.m8n8.x4.shared.b16 {%0,%1,%2,%3}, [%4];"
                 : "=r"(r0), "=r"(r1), "=r"(r2), "=r"(r3) : "r"(addr));
}
__device__ __forceinline__ void mma_fp16(float& c0, float& c1, float& c2, float& c3,
                                         uint32_t a0, uint32_t a1, uint32_t a2, uint32_t a3,
                                         uint32_t b0, uint32_t b1) {
    asm volatile(
        "mma.sync.aligned.m16n8k16.row.col.f32.f16.f16.f32 "
        "{%0,%1,%2,%3}, {%4,%5,%6,%7}, {%8,%9}, {%0,%1,%2,%3};"
        : "+f"(c0), "+f"(c1), "+f"(c2), "+f"(c3)
        : "r"(a0), "r"(a1), "r"(a2), "r"(a3), "r"(b0), "r"(b1));
}
__device__ __forceinline__ uint2 pack_h4(float4 v) {
    __half2 p0 = __floats2half2_rn(v.x, v.y);
    __half2 p1 = __floats2half2_rn(v.z, v.w);
    uint2 u;
    u.x = *(uint32_t*)&p0;
    u.y = *(uint32_t*)&p1;
    return u;
}

// ---------------------------------------------------------------------------
// Kernel 0: convert x to fp16 (DRAM-bound, 16 regs, high occupancy)
// ---------------------------------------------------------------------------
__global__ __launch_bounds__(256) void convert_x_kernel(const float* __restrict__ x)
{
    size_t i4 = (size_t)blockIdx.x * 256 + threadIdx.x;   // float4 index
    float4 v = __ldg((const float4*)x + i4);
    *(uint2*)&g_Xh[i4 * 4] = pack_h4(v);
}

// ---------------------------------------------------------------------------
// Kernel 1: fold LoRA into W, output fp16. 128x128 tile (proven fastest).
//   Weff[o,d] = W[o,d] + sum_k Bs[o,k] * A[k,d],  k = 16e + r, Bs masked
// ---------------------------------------------------------------------------
__global__ __launch_bounds__(256) void fold_kernel(
    const float* __restrict__ W,
    const float* __restrict__ A,          // lora_A as [128, D_IN]
    const float* __restrict__ Bl,         // [E, D_OUT, R]
    const int* __restrict__ mask)
{
    __shared__ __align__(16) float sB[16][132];
    __shared__ __align__(16) float sA[16][132];

    const int t  = threadIdx.x;
    const int tr = t >> 4;
    const int tc = t & 15;
    const int o0 = blockIdx.y * 128;
    const int d0 = blockIdx.x * 128;

    float acc[8][8];
#pragma unroll
    for (int i = 0; i < 8; ++i)
#pragma unroll
        for (int j = 0; j < 8; ++j) acc[i][j] = 0.f;

    for (int c = 0; c < NEXP; ++c) {
        const float sc = (mask[c] != 0) ? SCALING : 0.f;
#pragma unroll
        for (int i = 0; i < 8; ++i) {
            int idx = t + i * 256;
            int ol = idx >> 4, r = idx & 15;
            sB[r][ol] = Bl[(size_t)c * D_OUT * RANK + (size_t)(o0 + ol) * RANK + r] * sc;
        }
#pragma unroll
        for (int i = 0; i < 8; ++i) {
            int idx = t + i * 256;
            int kk = idx >> 7, dl = idx & 127;
            sA[kk][dl] = A[(size_t)(c * 16 + kk) * D_IN + d0 + dl];
        }
        __syncthreads();
#pragma unroll
        for (int kk = 0; kk < 16; ++kk) {
            float4 b0 = *(const float4*)&sB[kk][tr * 8];
            float4 b1 = *(const float4*)&sB[kk][tr * 8 + 4];
            float4 a0 = *(const float4*)&sA[kk][tc * 8];
            float4 a1 = *(const float4*)&sA[kk][tc * 8 + 4];
            float ov[8] = {b0.x, b0.y, b0.z, b0.w, b1.x, b1.y, b1.z, b1.w};
            float dv[8] = {a0.x, a0.y, a0.z, a0.w, a1.x, a1.y, a1.z, a1.w};
#pragma unroll
            for (int i = 0; i < 8; ++i)
#pragma unroll
                for (int j = 0; j < 8; ++j) acc[i][j] += ov[i] * dv[j];
        }
        __syncthreads();
    }

#pragma unroll
    for (int i = 0; i < 8; ++i) {
        int o = o0 + tr * 8 + i;
#pragma unroll
        for (int j = 0; j < 8; j += 4) {
            int d = d0 + tc * 8 + j;
            float4 w = *(const float4*)&W[(size_t)o * D_IN + d];
            float4 r;
            r.x = w.x + acc[i][j + 0]; r.y = w.y + acc[i][j + 1];
            r.z = w.z + acc[i][j + 2]; r.w = w.w + acc[i][j + 3];
            *(uint2*)&g_Wh[(size_t)o * D_IN + d] = pack_h4(r);
        }
    }
}

// ---------------------------------------------------------------------------
// Kernel 2: fp16 GEMM via mma.sync.m16n8k16 (fp32 accumulate).
//   out[m,n] = sum_k x[m,k]*Weff[n,k] + bias[n]
// BM=128 BN=128 BK=64, 256 threads = 8 warps (2m x 4n), warp tile 64x32.
// 3-stage cp.async pipeline, ONE __syncthreads per K-iter.  (round-6 proven)
// Rows are 128B; swizzle: seg' = seg ^ (row&7) -> conflict-free ldmatrix.
// ---------------------------------------------------------------------------
#define BK 64
#define NKT (D_IN / BK)            // 32
#define TILE_B 16384               // bytes per tile (128 rows x 128B)
#define STG_B  (2 * TILE_B)        // 32KB per stage (X + W)
#define NSTG   3
#define SMEM_B (NSTG * STG_B)      // 96KB

__global__ __launch_bounds__(256, 2)
void gemm_mma_kernel(const float* __restrict__ bias, float* __restrict__ out)
{
    extern __shared__ __align__(1024) char smem[];
    const uint32_t sb = smem_u32(smem);

    const int t    = threadIdx.x;
    const int lane = t & 31;
    const int wid  = t >> 5;
    const int wm0  = (wid >> 2) * 64;     // warp m offset in tile
    const int wn0  = (wid & 3) * 32;      // warp n offset in tile
    const int n0   = blockIdx.x * 128;
    const int m0   = blockIdx.y * 128;

    // ldmatrix lane geometry
    const int a_row = wm0 + (lane & 7) + ((lane >> 3) & 1) * 8;  // + mi*16
    const int a_ks  = (lane >> 4);                               // + 2*j
    const int b_row = wn0 + (lane & 7) + (lane >> 4) * 8;        // + ni2*16
    const int b_ks  = (lane >> 3) & 1;                           // + 2*j
    const int a_r7  = a_row & 7;
    const int b_r7  = b_row & 7;

    float acc[4][4][4];
#pragma unroll
    for (int i = 0; i < 4; ++i)
#pragma unroll
        for (int j = 0; j < 4; ++j)
#pragma unroll
            for (int q = 0; q < 4; ++q) acc[i][j][q] = 0.f;

    // cp.async: per stage 2 tiles x 1024 chunks of 16B; 8 chunks per thread.
    auto issue_stage = [&](int kt, int stg) {
        const uint32_t base = sb + stg * STG_B;
        const int kbase = kt * BK;
#pragma unroll
        for (int ii = 0; ii < 4; ++ii) {
            int c = t + ii * 256;
            int row = c >> 3, seg = c & 7;
            uint32_t soff = (uint32_t)(row * 128 + ((seg ^ (row & 7)) << 4));
            cpa16(base + soff,
                  &g_Xh[(size_t)(m0 + row) * D_IN + kbase + seg * 8]);
            cpa16(base + TILE_B + soff,
                  &g_Wh[(size_t)(n0 + row) * D_IN + kbase + seg * 8]);
        }
        cpa_commit();
    };

    issue_stage(0, 0);
    issue_stage(1, 1);

    int stg = 0, stg2 = 2;   // stage of kt, stage of kt+2 (rotating mod 3)
    for (int kt = 0; kt < NKT; ++kt) {
        // group for stage kt must be complete
        if (kt == NKT - 1) cpa_wait<0>(); else cpa_wait<1>();
        __syncthreads();    // all warps done with stage (kt-1); safe to refill it

        if (kt + 2 < NKT) issue_stage(kt + 2, stg2);

        const uint32_t xh = sb + stg * STG_B;
        const uint32_t wh = xh + TILE_B;

#pragma unroll
        for (int j = 0; j < 4; ++j) {               // k16 steps within BK=64
            uint32_t ah[4][4];
            const int aks = 2 * j + a_ks;
            const uint32_t axoff = (uint32_t)((aks ^ a_r7) << 4);
#pragma unroll
            for (int mi = 0; mi < 4; ++mi) {
                const uint32_t ro = (uint32_t)((a_row + mi * 16) * 128) + axoff;
                ldsm_x4(xh + ro, ah[mi][0], ah[mi][1], ah[mi][2], ah[mi][3]);
            }
            uint32_t bh[2][4];
            const int bks = 2 * j + b_ks;
            const uint32_t bxoff = (uint32_t)((bks ^ b_r7) << 4);
#pragma unroll
            for (int ni2 = 0; ni2 < 2; ++ni2) {
                const uint32_t ro = (uint32_t)((b_row + ni2 * 16) * 128) + bxoff;
                ldsm_x4(wh + ro, bh[ni2][0], bh[ni2][1], bh[ni2][2], bh[ni2][3]);
            }
#pragma unroll
            for (int mi = 0; mi < 4; ++mi) {
#pragma unroll
                for (int ni = 0; ni < 4; ++ni) {
                    const int g = ni >> 1, o = (ni & 1) * 2;
                    float* c = acc[mi][ni];
                    mma_fp16(c[0], c[1], c[2], c[3],
                             ah[mi][0], ah[mi][1], ah[mi][2], ah[mi][3],
                             bh[g][o], bh[g][o + 1]);
                }
            }
        }

        stg  = (stg  == 2) ? 0 : stg  + 1;
        stg2 = (stg2 == 2) ? 0 : stg2 + 1;
    }

    // Epilogue: c layout m16n8: c0,c1 at (row=lane>>2, col=(lane&3)*2), c2,c3 at row+8.
    const int erow = lane >> 2;
    const int ecol = (lane & 3) * 2;
#pragma unroll
    for (int ni = 0; ni < 4; ++ni) {
        const int ncol = n0 + wn0 + ni * 8 + ecol;
        const float b0 = __ldg(&bias[ncol]);
        const float b1 = __ldg(&bias[ncol + 1]);
#pragma unroll
        for (int mi = 0; mi < 4; ++mi) {
            const int r0 = m0 + wm0 + mi * 16 + erow;
            float2 v0 = { acc[mi][ni][0] + b0, acc[mi][ni][1] + b1 };
            float2 v1 = { acc[mi][ni][2] + b0, acc[mi][ni][3] + b1 };
            *(float2*)&out[(size_t)r0 * D_OUT + ncol] = v0;
            *(float2*)&out[(size_t)(r0 + 8) * D_OUT + ncol] = v1;
        }
    }
}

// ---------------------------------------------------------------------------
// Inputs (metadata order): x, W, b, lora_A, lora_B, expert_mask
// ---------------------------------------------------------------------------
extern "C" void kernel_launch(void* const* d_in, const int* in_sizes, int n_in,
                              void* d_out, int out_size)
{
    const float* x    = (const float*)d_in[0];
    const float* W    = (const float*)d_in[1];
    const float* b    = (const float*)d_in[2];
    const float* lA   = (const float*)d_in[3];
    const float* lB   = (const float*)d_in[4];
    const int*   mask = (const int*)d_in[5];
    float* out = (float*)d_out;

    static bool attr_done = false;
    if (!attr_done) {
        cudaFuncSetAttribute(gemm_mma_kernel,
                             cudaFuncAttributeMaxDynamicSharedMemorySize, SMEM_B);
        attr_done = true;
    }

    dim3 blk(256);
    convert_x_kernel<<<(M_TOK * D_IN / 4) / 256, blk>>>(x);
    dim3 grid_fold(D_IN / 128, D_OUT / 128);    // (16, 16) = 256 blocks
    fold_kernel<<<grid_fold, blk>>>(W, lA, lB, mask);
    dim3 grid_gemm(D_OUT / 128, M_TOK / 128);   // (16, 64)
    gemm_mma_kernel<<<grid_gemm, blk, SMEM_B>>>(b, out);
}

// round 10
// speedup vs baseline: 1.3627x; 1.1614x over previous
#include <cuda_runtime.h>
#include <cuda_fp16.h>
#include <cstdint>

#define D_IN   2048
#define D_OUT  2048
#define M_TOK  8192
#define RANK   16
#define NEXP   8
#define SCALING 1.0f

// fp16 operands, precomputed. Static device globals (no runtime alloc).
__device__ __half g_Xh[(size_t)M_TOK * D_IN];
__device__ __half g_Wh[(size_t)D_OUT * D_IN];
__device__ __half g_Bsh[(size_t)D_OUT * 128];   // [o][k=16e+r], masked
__device__ __half g_Ath[(size_t)D_IN * 128];    // [d][k]  (lora_A transposed)

// ---------------------------------------------------------------------------
// helpers
// ---------------------------------------------------------------------------
__device__ __forceinline__ uint32_t smem_u32(const void* p) {
    uint32_t a;
    asm("{ .reg .u64 t; cvta.to.shared.u64 t, %1; cvt.u32.u64 %0, t; }" : "=r"(a) : "l"(p));
    return a;
}
__device__ __forceinline__ void cpa16(uint32_t s, const void* g) {
    asm volatile("cp.async.cg.shared.global [%0], [%1], 16;" :: "r"(s), "l"(g));
}
__device__ __forceinline__ void cpa_commit() {
    asm volatile("cp.async.commit_group;" ::: "memory");
}
template <int N> __device__ __forceinline__ void cpa_wait() {
    asm volatile("cp.async.wait_group %0;" :: "n"(N) : "memory");
}
__device__ __forceinline__ void ldsm_x4(uint32_t addr, uint32_t& r0, uint32_t& r1,
                                        uint32_t& r2, uint32_t& r3) {
    asm volatile("ldmatrix.sync.aligned.m8n8.x4.shared.b16 {%0,%1,%2,%3}, [%4];"
                 : "=r"(r0), "=r"(r1), "=r"(r2), "=r"(r3) : "r"(addr));
}
__device__ __forceinline__ void mma_fp16(float& c0, float& c1, float& c2, float& c3,
                                         uint32_t a0, uint32_t a1, uint32_t a2, uint32_t a3,
                                         uint32_t b0, uint32_t b1) {
    asm volatile(
        "mma.sync.aligned.m16n8k16.row.col.f32.f16.f16.f32 "
        "{%0,%1,%2,%3}, {%4,%5,%6,%7}, {%8,%9}, {%0,%1,%2,%3};"
        : "+f"(c0), "+f"(c1), "+f"(c2), "+f"(c3)
        : "r"(a0), "r"(a1), "r"(a2), "r"(a3), "r"(b0), "r"(b1));
}
__device__ __forceinline__ uint2 pack_h4(float4 v) {
    __half2 p0 = __floats2half2_rn(v.x, v.y);
    __half2 p1 = __floats2half2_rn(v.z, v.w);
    uint2 u;
    u.x = *(uint32_t*)&p0;
    u.y = *(uint32_t*)&p1;
    return u;
}

// ---------------------------------------------------------------------------
// Kernel 0 (merged prep, all branches low-reg):
//  blocks [0, NCONV): convert x -> fp16
//  blocks [NCONV, NCONV+NAT): transpose lora_A -> Ath[d][k] fp16
//  blocks [NCONV+NAT, NCONV+NAT+NBS): build masked Bsh[o][k] fp16
// ---------------------------------------------------------------------------
#define NCONV ((M_TOK * D_IN / 4) / 256)   // 16384
#define NAT   128                          // 128 blocks x 16 d-cols
#define NBS   64                           // 64 blocks x 32 o-rows

__global__ __launch_bounds__(256) void prep_kernel(
    const float* __restrict__ x,
    const float* __restrict__ A,          // lora_A as [128, D_IN]
    const float* __restrict__ Bl,         // [E, D_OUT, R]
    const int* __restrict__ mask)
{
    const int t = threadIdx.x;
    const unsigned b = blockIdx.x;

    if (b < NCONV) {
        size_t i4 = (size_t)b * 256 + t;
        float4 v = __ldg((const float4*)x + i4);
        *(uint2*)&g_Xh[i4 * 4] = pack_h4(v);
        return;
    }
    if (b < NCONV + NAT) {
        // Ath[d][k] = A[k][d]; block covers d0..d0+15, all 128 k.
        const int d0 = (int)(b - NCONV) * 16;
        const int k  = t >> 1;              // 0..127
        const int dg = (t & 1) * 8;         // 0 or 8
        float4 v0 = __ldg((const float4*)&A[(size_t)k * D_IN + d0 + dg]);
        float4 v1 = __ldg((const float4*)&A[(size_t)k * D_IN + d0 + dg + 4]);
        float vv[8] = {v0.x, v0.y, v0.z, v0.w, v1.x, v1.y, v1.z, v1.w};
#pragma unroll
        for (int j = 0; j < 8; ++j)
            g_Ath[(size_t)(d0 + dg + j) * 128 + k] = __float2half_rn(vv[j]);
        return;
    }
    {
        // Bsh[o][16e+r] = mask[e] * Bl[e][o][r]; block covers 32 o-rows.
        const int o = (int)(b - NCONV - NAT) * 32 + (t >> 3);
        const int e = t & 7;
        const float sc = (__ldg(&mask[e]) != 0) ? SCALING : 0.f;
        const float* src = &Bl[(size_t)e * D_OUT * RANK + (size_t)o * RANK];
        uint2 hv[2];
#pragma unroll
        for (int h = 0; h < 2; ++h) {
            float4 v = __ldg((const float4*)(src + h * 8));
            float4 w = __ldg((const float4*)(src + h * 8 + 4));
            v.x *= sc; v.y *= sc; v.z *= sc; v.w *= sc;
            w.x *= sc; w.y *= sc; w.z *= sc; w.w *= sc;
            uint2 a = pack_h4(v), c = pack_h4(w);
            hv[h].x = a.x; hv[h].y = a.y;
            // store 8 halfs = 4 uints
            uint32_t* dst = (uint32_t*)&g_Bsh[(size_t)o * 128 + e * 16 + h * 8];
            dst[0] = a.x; dst[1] = a.y; dst[2] = c.x; dst[3] = c.y;
        }
    }
}

// ---------------------------------------------------------------------------
// Kernel 1: fold via tensor cores.
//   Weff[o,d] = W[o,d] + sum_{k<128} Bsh[o,k] * Ath[d,k]
// Structural clone of the main GEMM: tile 128(o) x 128(d), K=128 = 2 x BK64,
// 8 warps (2m x 4n), warp 64x32, same swizzle + non-trans ldsm mapping.
// ---------------------------------------------------------------------------
#define FTILE_B 16384              // 128 rows x 128B per stage-tile
#define FSTG_B  (2 * FTILE_B)      // 32KB per stage
#define FSMEM_B (2 * FSTG_B)       // 64KB

__global__ __launch_bounds__(256, 2)
void fold_mma_kernel(const float* __restrict__ W)
{
    extern __shared__ __align__(1024) char smem[];
    const uint32_t sb = smem_u32(smem);

    const int t    = threadIdx.x;
    const int lane = t & 31;
    const int wid  = t >> 5;
    const int wm0  = (wid >> 2) * 64;     // o offset in tile
    const int wn0  = (wid & 3) * 32;      // d offset in tile
    const int d0   = blockIdx.x * 128;
    const int o0   = blockIdx.y * 128;

    const int a_row = wm0 + (lane & 7) + ((lane >> 3) & 1) * 8;
    const int a_ks  = (lane >> 4);
    const int b_row = wn0 + (lane & 7) + (lane >> 4) * 8;
    const int b_ks  = (lane >> 3) & 1;
    const int a_r7  = a_row & 7;
    const int b_r7  = b_row & 7;

    float acc[4][4][4];
#pragma unroll
    for (int i = 0; i < 4; ++i)
#pragma unroll
        for (int j = 0; j < 4; ++j)
#pragma unroll
            for (int q = 0; q < 4; ++q) acc[i][j][q] = 0.f;

    // Load both K-chunks (row stride = 128 halfs).
#pragma unroll
    for (int s = 0; s < 2; ++s) {
        const uint32_t base = sb + s * FSTG_B;
        const int kbase = s * 64;
#pragma unroll
        for (int ii = 0; ii < 4; ++ii) {
            int c = t + ii * 256;
            int row = c >> 3, seg = c & 7;
            uint32_t soff = (uint32_t)(row * 128 + ((seg ^ (row & 7)) << 4));
            cpa16(base + soff, &g_Bsh[(size_t)(o0 + row) * 128 + kbase + seg * 8]);
            cpa16(base + FTILE_B + soff, &g_Ath[(size_t)(d0 + row) * 128 + kbase + seg * 8]);
        }
    }
    cpa_commit();
    cpa_wait<0>();
    __syncthreads();

#pragma unroll
    for (int s = 0; s < 2; ++s) {
        const uint32_t xh = sb + s * FSTG_B;
        const uint32_t wh = xh + FTILE_B;
#pragma unroll
        for (int j = 0; j < 4; ++j) {
            uint32_t ah[4][4];
            const int aks = 2 * j + a_ks;
            const uint32_t axoff = (uint32_t)((aks ^ a_r7) << 4);
#pragma unroll
            for (int mi = 0; mi < 4; ++mi) {
                const uint32_t ro = (uint32_t)((a_row + mi * 16) * 128) + axoff;
                ldsm_x4(xh + ro, ah[mi][0], ah[mi][1], ah[mi][2], ah[mi][3]);
            }
            uint32_t bh[2][4];
            const int bks = 2 * j + b_ks;
            const uint32_t bxoff = (uint32_t)((bks ^ b_r7) << 4);
#pragma unroll
            for (int ni2 = 0; ni2 < 2; ++ni2) {
                const uint32_t ro = (uint32_t)((b_row + ni2 * 16) * 128) + bxoff;
                ldsm_x4(wh + ro, bh[ni2][0], bh[ni2][1], bh[ni2][2], bh[ni2][3]);
            }
#pragma unroll
            for (int mi = 0; mi < 4; ++mi) {
#pragma unroll
                for (int ni = 0; ni < 4; ++ni) {
                    const int g = ni >> 1, o = (ni & 1) * 2;
                    float* c = acc[mi][ni];
                    mma_fp16(c[0], c[1], c[2], c[3],
                             ah[mi][0], ah[mi][1], ah[mi][2], ah[mi][3],
                             bh[g][o], bh[g][o + 1]);
                }
            }
        }
    }

    // Epilogue: Wh[o][d] = fp16(W[o][d] + acc)
    const int erow = lane >> 2;
    const int ecol = (lane & 3) * 2;
#pragma unroll
    for (int ni = 0; ni < 4; ++ni) {
        const int dcol = d0 + wn0 + ni * 8 + ecol;
#pragma unroll
        for (int mi = 0; mi < 4; ++mi) {
            const int orow = o0 + wm0 + mi * 16 + erow;
#pragma unroll
            for (int h = 0; h < 2; ++h) {
                const int r = orow + h * 8;
                float2 w = __ldg((const float2*)&W[(size_t)r * D_IN + dcol]);
                __half2 p = __floats2half2_rn(w.x + acc[mi][ni][h * 2 + 0],
                                              w.y + acc[mi][ni][h * 2 + 1]);
                *(uint32_t*)&g_Wh[(size_t)r * D_IN + dcol] = *(uint32_t*)&p;
            }
        }
    }
}

// ---------------------------------------------------------------------------
// Kernel 2: main fp16 GEMM (round-6 proven, 156.5us @ 72.6% tensor).
//   out[m,n] = sum_k x[m,k]*Weff[n,k] + bias[n]
// BM=128 BN=128 BK=64, 8 warps (2m x 4n), warp 64x32, 3-stage cp.async.
// ---------------------------------------------------------------------------
#define BK 64
#define NKT (D_IN / BK)            // 32
#define TILE_B 16384
#define STG_B  (2 * TILE_B)
#define NSTG   3
#define SMEM_B (NSTG * STG_B)      // 96KB

__global__ __launch_bounds__(256, 2)
void gemm_mma_kernel(const float* __restrict__ bias, float* __restrict__ out)
{
    extern __shared__ __align__(1024) char smem[];
    const uint32_t sb = smem_u32(smem);

    const int t    = threadIdx.x;
    const int lane = t & 31;
    const int wid  = t >> 5;
    const int wm0  = (wid >> 2) * 64;
    const int wn0  = (wid & 3) * 32;
    const int n0   = blockIdx.x * 128;
    const int m0   = blockIdx.y * 128;

    const int a_row = wm0 + (lane & 7) + ((lane >> 3) & 1) * 8;
    const int a_ks  = (lane >> 4);
    const int b_row = wn0 + (lane & 7) + (lane >> 4) * 8;
    const int b_ks  = (lane >> 3) & 1;
    const int a_r7  = a_row & 7;
    const int b_r7  = b_row & 7;

    float acc[4][4][4];
#pragma unroll
    for (int i = 0; i < 4; ++i)
#pragma unroll
        for (int j = 0; j < 4; ++j)
#pragma unroll
            for (int q = 0; q < 4; ++q) acc[i][j][q] = 0.f;

    auto issue_stage = [&](int kt, int stg) {
        const uint32_t base = sb + stg * STG_B;
        const int kbase = kt * BK;
#pragma unroll
        for (int ii = 0; ii < 4; ++ii) {
            int c = t + ii * 256;
            int row = c >> 3, seg = c & 7;
            uint32_t soff = (uint32_t)(row * 128 + ((seg ^ (row & 7)) << 4));
            cpa16(base + soff,
                  &g_Xh[(size_t)(m0 + row) * D_IN + kbase + seg * 8]);
            cpa16(base + TILE_B + soff,
                  &g_Wh[(size_t)(n0 + row) * D_IN + kbase + seg * 8]);
        }
        cpa_commit();
    };

    issue_stage(0, 0);
    issue_stage(1, 1);

    int stg = 0, stg2 = 2;
    for (int kt = 0; kt < NKT; ++kt) {
        if (kt == NKT - 1) cpa_wait<0>(); else cpa_wait<1>();
        __syncthreads();

        if (kt + 2 < NKT) issue_stage(kt + 2, stg2);

        const uint32_t xh = sb + stg * STG_B;
        const uint32_t wh = xh + TILE_B;

#pragma unroll
        for (int j = 0; j < 4; ++j) {
            uint32_t ah[4][4];
            const int aks = 2 * j + a_ks;
            const uint32_t axoff = (uint32_t)((aks ^ a_r7) << 4);
#pragma unroll
            for (int mi = 0; mi < 4; ++mi) {
                const uint32_t ro = (uint32_t)((a_row + mi * 16) * 128) + axoff;
                ldsm_x4(xh + ro, ah[mi][0], ah[mi][1], ah[mi][2], ah[mi][3]);
            }
            uint32_t bh[2][4];
            const int bks = 2 * j + b_ks;
            const uint32_t bxoff = (uint32_t)((bks ^ b_r7) << 4);
#pragma unroll
            for (int ni2 = 0; ni2 < 2; ++ni2) {
                const uint32_t ro = (uint32_t)((b_row + ni2 * 16) * 128) + bxoff;
                ldsm_x4(wh + ro, bh[ni2][0], bh[ni2][1], bh[ni2][2], bh[ni2][3]);
            }
#pragma unroll
            for (int mi = 0; mi < 4; ++mi) {
#pragma unroll
                for (int ni = 0; ni < 4; ++ni) {
                    const int g = ni >> 1, o = (ni & 1) * 2;
                    float* c = acc[mi][ni];
                    mma_fp16(c[0], c[1], c[2], c[3],
                             ah[mi][0], ah[mi][1], ah[mi][2], ah[mi][3],
                             bh[g][o], bh[g][o + 1]);
                }
            }
        }

        stg  = (stg  == 2) ? 0 : stg  + 1;
        stg2 = (stg2 == 2) ? 0 : stg2 + 1;
    }

    const int erow = lane >> 2;
    const int ecol = (lane & 3) * 2;
#pragma unroll
    for (int ni = 0; ni < 4; ++ni) {
        const int ncol = n0 + wn0 + ni * 8 + ecol;
        const float b0 = __ldg(&bias[ncol]);
        const float b1 = __ldg(&bias[ncol + 1]);
#pragma unroll
        for (int mi = 0; mi < 4; ++mi) {
            const int r0 = m0 + wm0 + mi * 16 + erow;
            float2 v0 = { acc[mi][ni][0] + b0, acc[mi][ni][1] + b1 };
            float2 v1 = { acc[mi][ni][2] + b0, acc[mi][ni][3] + b1 };
            *(float2*)&out[(size_t)r0 * D_OUT + ncol] = v0;
            *(float2*)&out[(size_t)(r0 + 8) * D_OUT + ncol] = v1;
        }
    }
}

// ---------------------------------------------------------------------------
// Inputs (metadata order): x, W, b, lora_A, lora_B, expert_mask
// ---------------------------------------------------------------------------
extern "C" void kernel_launch(void* const* d_in, const int* in_sizes, int n_in,
                              void* d_out, int out_size)
{
    const float* x    = (const float*)d_in[0];
    const float* W    = (const float*)d_in[1];
    const float* b    = (const float*)d_in[2];
    const float* lA   = (const float*)d_in[3];
    const float* lB   = (const float*)d_in[4];
    const int*   mask = (const int*)d_in[5];
    float* out = (float*)d_out;

    static bool attr_done = false;
    if (!attr_done) {
        cudaFuncSetAttribute(gemm_mma_kernel,
                             cudaFuncAttributeMaxDynamicSharedMemorySize, SMEM_B);
        cudaFuncSetAttribute(fold_mma_kernel,
                             cudaFuncAttributeMaxDynamicSharedMemorySize, FSMEM_B);
        attr_done = true;
    }

    dim3 blk(256);
    prep_kernel<<<NCONV + NAT + NBS, blk>>>(x, lA, lB, mask);
    dim3 grid_fold(D_IN / 128, D_OUT / 128);    // (16, 16)
    fold_mma_kernel<<<grid_fold, blk, FSMEM_B>>>(W);
    dim3 grid_gemm(D_OUT / 128, M_TOK / 128);   // (16, 64)
    gemm_mma_kernel<<<grid_gemm, blk, SMEM_B>>>(b, out);
}

// round 11
// speedup vs baseline: 1.3795x; 1.0123x over previous
#include <cuda_runtime.h>
#include <cuda_fp16.h>
#include <cstdint>

#define D_IN   2048
#define D_OUT  2048
#define M_TOK  8192
#define RANK   16
#define NEXP   8
#define SCALING 1.0f

// fp16 operands, precomputed. Static device globals (no runtime alloc).
__device__ __half g_Xh[(size_t)M_TOK * D_IN];
__device__ __half g_Wh[(size_t)D_OUT * D_IN];
__device__ __half g_Bsh[(size_t)D_OUT * 128];   // [o][k=16e+r], masked
__device__ __half g_Ath[(size_t)D_IN * 128];    // [d][k]  (lora_A transposed)

// ---------------------------------------------------------------------------
// helpers
// ---------------------------------------------------------------------------
__device__ __forceinline__ uint32_t smem_u32(const void* p) {
    uint32_t a;
    asm("{ .reg .u64 t; cvta.to.shared.u64 t, %1; cvt.u32.u64 %0, t; }" : "=r"(a) : "l"(p));
    return a;
}
__device__ __forceinline__ void cpa16(uint32_t s, const void* g) {
    asm volatile("cp.async.cg.shared.global [%0], [%1], 16;" :: "r"(s), "l"(g));
}
__device__ __forceinline__ void cpa_commit() {
    asm volatile("cp.async.commit_group;" ::: "memory");
}
template <int N> __device__ __forceinline__ void cpa_wait() {
    asm volatile("cp.async.wait_group %0;" :: "n"(N) : "memory");
}
__device__ __forceinline__ void ldsm_x4(uint32_t addr, uint32_t& r0, uint32_t& r1,
                                        uint32_t& r2, uint32_t& r3) {
    asm volatile("ldmatrix.sync.aligned.m8n8.x4.shared.b16 {%0,%1,%2,%3}, [%4];"
                 : "=r"(r0), "=r"(r1), "=r"(r2), "=r"(r3) : "r"(addr));
}
__device__ __forceinline__ void mma_fp16(float& c0, float& c1, float& c2, float& c3,
                                         uint32_t a0, uint32_t a1, uint32_t a2, uint32_t a3,
                                         uint32_t b0, uint32_t b1) {
    asm volatile(
        "mma.sync.aligned.m16n8k16.row.col.f32.f16.f16.f32 "
        "{%0,%1,%2,%3}, {%4,%5,%6,%7}, {%8,%9}, {%0,%1,%2,%3};"
        : "+f"(c0), "+f"(c1), "+f"(c2), "+f"(c3)
        : "r"(a0), "r"(a1), "r"(a2), "r"(a3), "r"(b0), "r"(b1));
}
__device__ __forceinline__ uint2 pack_h4(float4 v) {
    __half2 p0 = __floats2half2_rn(v.x, v.y);
    __half2 p1 = __floats2half2_rn(v.z, v.w);
    uint2 u;
    u.x = *(uint32_t*)&p0;
    u.y = *(uint32_t*)&p1;
    return u;
}

// ---------------------------------------------------------------------------
// Kernel 0 (merged prep):
//  blocks [0, NCONV): convert x -> fp16 (2 float4/thread for MLP)
//  blocks [NCONV, NCONV+NAT): transpose lora_A -> Ath[d][k] fp16
//  blocks [NCONV+NAT, ...): build masked Bsh[o][k] fp16
// ---------------------------------------------------------------------------
#define NCONV ((M_TOK * D_IN / 8) / 256)   // 8192 blocks, 2 float4/thread
#define NAT   128
#define NBS   64

__global__ __launch_bounds__(256) void prep_kernel(
    const float* __restrict__ x,
    const float* __restrict__ A,          // lora_A as [128, D_IN]
    const float* __restrict__ Bl,         // [E, D_OUT, R]
    const int* __restrict__ mask)
{
    const int t = threadIdx.x;
    const unsigned b = blockIdx.x;

    if (b < NCONV) {
        size_t i4 = (size_t)b * 512 + t;
        float4 v0 = __ldg((const float4*)x + i4);
        float4 v1 = __ldg((const float4*)x + i4 + 256);
        *(uint2*)&g_Xh[i4 * 4] = pack_h4(v0);
        *(uint2*)&g_Xh[(i4 + 256) * 4] = pack_h4(v1);
        return;
    }
    if (b < NCONV + NAT) {
        // Ath[d][k] = A[k][d]; block covers d0..d0+15, all 128 k.
        const int d0 = (int)(b - NCONV) * 16;
        const int k  = t >> 1;              // 0..127
        const int dg = (t & 1) * 8;         // 0 or 8
        float4 v0 = __ldg((const float4*)&A[(size_t)k * D_IN + d0 + dg]);
        float4 v1 = __ldg((const float4*)&A[(size_t)k * D_IN + d0 + dg + 4]);
        float vv[8] = {v0.x, v0.y, v0.z, v0.w, v1.x, v1.y, v1.z, v1.w};
#pragma unroll
        for (int j = 0; j < 8; ++j)
            g_Ath[(size_t)(d0 + dg + j) * 128 + k] = __float2half_rn(vv[j]);
        return;
    }
    {
        // Bsh[o][16e+r] = mask[e] * Bl[e][o][r]; block covers 32 o-rows.
        const int o = (int)(b - NCONV - NAT) * 32 + (t >> 3);
        const int e = t & 7;
        const float sc = (__ldg(&mask[e]) != 0) ? SCALING : 0.f;
        const float* src = &Bl[(size_t)e * D_OUT * RANK + (size_t)o * RANK];
#pragma unroll
        for (int h = 0; h < 2; ++h) {
            float4 v = __ldg((const float4*)(src + h * 8));
            float4 w = __ldg((const float4*)(src + h * 8 + 4));
            v.x *= sc; v.y *= sc; v.z *= sc; v.w *= sc;
            w.x *= sc; w.y *= sc; w.z *= sc; w.w *= sc;
            uint2 a = pack_h4(v), c = pack_h4(w);
            uint32_t* dst = (uint32_t*)&g_Bsh[(size_t)o * 128 + e * 16 + h * 8];
            dst[0] = a.x; dst[1] = a.y; dst[2] = c.x; dst[3] = c.y;
        }
    }
}

// ---------------------------------------------------------------------------
// Kernel 1: fold via tensor cores (proven round 10).
//   Weff[o,d] = W[o,d] + sum_{k<128} Bsh[o,k] * Ath[d,k]
// ---------------------------------------------------------------------------
#define FTILE_B 16384
#define FSTG_B  (2 * FTILE_B)
#define FSMEM_B (2 * FSTG_B)       // 64KB

__global__ __launch_bounds__(256, 2)
void fold_mma_kernel(const float* __restrict__ W)
{
    extern __shared__ __align__(1024) char smem[];
    const uint32_t sb = smem_u32(smem);

    const int t    = threadIdx.x;
    const int lane = t & 31;
    const int wid  = t >> 5;
    const int wm0  = (wid >> 2) * 64;
    const int wn0  = (wid & 3) * 32;
    const int d0   = blockIdx.x * 128;
    const int o0   = blockIdx.y * 128;

    const int a_row = wm0 + (lane & 7) + ((lane >> 3) & 1) * 8;
    const int a_ks  = (lane >> 4);
    const int b_row = wn0 + (lane & 7) + (lane >> 4) * 8;
    const int b_ks  = (lane >> 3) & 1;
    const int a_r7  = a_row & 7;
    const int b_r7  = b_row & 7;

    float acc[4][4][4];
#pragma unroll
    for (int i = 0; i < 4; ++i)
#pragma unroll
        for (int j = 0; j < 4; ++j)
#pragma unroll
            for (int q = 0; q < 4; ++q) acc[i][j][q] = 0.f;

#pragma unroll
    for (int s = 0; s < 2; ++s) {
        const uint32_t base = sb + s * FSTG_B;
        const int kbase = s * 64;
#pragma unroll
        for (int ii = 0; ii < 4; ++ii) {
            int c = t + ii * 256;
            int row = c >> 3, seg = c & 7;
            uint32_t soff = (uint32_t)(row * 128 + ((seg ^ (row & 7)) << 4));
            cpa16(base + soff, &g_Bsh[(size_t)(o0 + row) * 128 + kbase + seg * 8]);
            cpa16(base + FTILE_B + soff, &g_Ath[(size_t)(d0 + row) * 128 + kbase + seg * 8]);
        }
    }
    cpa_commit();
    cpa_wait<0>();
    __syncthreads();

#pragma unroll
    for (int s = 0; s < 2; ++s) {
        const uint32_t xh = sb + s * FSTG_B;
        const uint32_t wh = xh + FTILE_B;
#pragma unroll
        for (int j = 0; j < 4; ++j) {
            uint32_t ah[4][4];
            const int aks = 2 * j + a_ks;
            const uint32_t axoff = (uint32_t)((aks ^ a_r7) << 4);
#pragma unroll
            for (int mi = 0; mi < 4; ++mi) {
                const uint32_t ro = (uint32_t)((a_row + mi * 16) * 128) + axoff;
                ldsm_x4(xh + ro, ah[mi][0], ah[mi][1], ah[mi][2], ah[mi][3]);
            }
            uint32_t bh[2][4];
            const int bks = 2 * j + b_ks;
            const uint32_t bxoff = (uint32_t)((bks ^ b_r7) << 4);
#pragma unroll
            for (int ni2 = 0; ni2 < 2; ++ni2) {
                const uint32_t ro = (uint32_t)((b_row + ni2 * 16) * 128) + bxoff;
                ldsm_x4(wh + ro, bh[ni2][0], bh[ni2][1], bh[ni2][2], bh[ni2][3]);
            }
#pragma unroll
            for (int mi = 0; mi < 4; ++mi) {
#pragma unroll
                for (int ni = 0; ni < 4; ++ni) {
                    const int g = ni >> 1, o = (ni & 1) * 2;
                    float* c = acc[mi][ni];
                    mma_fp16(c[0], c[1], c[2], c[3],
                             ah[mi][0], ah[mi][1], ah[mi][2], ah[mi][3],
                             bh[g][o], bh[g][o + 1]);
                }
            }
        }
    }

    const int erow = lane >> 2;
    const int ecol = (lane & 3) * 2;
#pragma unroll
    for (int ni = 0; ni < 4; ++ni) {
        const int dcol = d0 + wn0 + ni * 8 + ecol;
#pragma unroll
        for (int mi = 0; mi < 4; ++mi) {
            const int orow = o0 + wm0 + mi * 16 + erow;
#pragma unroll
            for (int h = 0; h < 2; ++h) {
                const int r = orow + h * 8;
                float2 w = __ldg((const float2*)&W[(size_t)r * D_IN + dcol]);
                __half2 p = __floats2half2_rn(w.x + acc[mi][ni][h * 2 + 0],
                                              w.y + acc[mi][ni][h * 2 + 1]);
                *(uint32_t*)&g_Wh[(size_t)r * D_IN + dcol] = *(uint32_t*)&p;
            }
        }
    }
}

// ---------------------------------------------------------------------------
// Kernel 2: main fp16 GEMM. NEW geometry: BM=64, BN=128, 128 threads
// (4 warps, each warp tile 64x32 — identical fragment machinery, wm0=0).
// 3-stage cp.async, 72KB smem -> 3 CTAs/SM. Grid 2048 CTAs (finer tail).
// ---------------------------------------------------------------------------
#define BK 64
#define NKT (D_IN / BK)            // 32
#define TILE_X_B 8192              // X tile: 64 rows x 128B
#define TILE_W_B 16384             // W tile: 128 rows x 128B
#define STG_B  (TILE_X_B + TILE_W_B)   // 24KB per stage
#define NSTG   3
#define SMEM_B (NSTG * STG_B)      // 72KB

__global__ __launch_bounds__(128, 3)
void gemm_mma_kernel(const float* __restrict__ bias, float* __restrict__ out)
{
    extern __shared__ __align__(1024) char smem[];
    const uint32_t sb = smem_u32(smem);

    const int t    = threadIdx.x;
    const int lane = t & 31;
    const int wid  = t >> 5;               // 0..3
    const int wn0  = wid * 32;             // warp n offset in tile
    const int n0   = blockIdx.x * 128;
    const int m0   = blockIdx.y * 64;

    // ldmatrix lane geometry (warp tile 64x32, wm0 = 0)
    const int a_row = (lane & 7) + ((lane >> 3) & 1) * 8;        // + mi*16
    const int a_ks  = (lane >> 4);                               // + 2*j
    const int b_row = wn0 + (lane & 7) + (lane >> 4) * 8;        // + ni2*16
    const int b_ks  = (lane >> 3) & 1;                           // + 2*j
    const int a_r7  = a_row & 7;
    const int b_r7  = b_row & 7;

    float acc[4][4][4];
#pragma unroll
    for (int i = 0; i < 4; ++i)
#pragma unroll
        for (int j = 0; j < 4; ++j)
#pragma unroll
            for (int q = 0; q < 4; ++q) acc[i][j][q] = 0.f;

    // cp.async: X 512 chunks (4/thread), W 1024 chunks (8/thread).
    auto issue_stage = [&](int kt, int stg) {
        const uint32_t base = sb + stg * STG_B;
        const int kbase = kt * BK;
#pragma unroll
        for (int ii = 0; ii < 4; ++ii) {
            int c = t + ii * 128;
            int row = c >> 3, seg = c & 7;
            uint32_t soff = (uint32_t)(row * 128 + ((seg ^ (row & 7)) << 4));
            cpa16(base + soff,
                  &g_Xh[(size_t)(m0 + row) * D_IN + kbase + seg * 8]);
        }
#pragma unroll
        for (int ii = 0; ii < 8; ++ii) {
            int c = t + ii * 128;
            int row = c >> 3, seg = c & 7;
            uint32_t soff = (uint32_t)(row * 128 + ((seg ^ (row & 7)) << 4));
            cpa16(base + TILE_X_B + soff,
                  &g_Wh[(size_t)(n0 + row) * D_IN + kbase + seg * 8]);
        }
        cpa_commit();
    };

    issue_stage(0, 0);
    issue_stage(1, 1);

    int stg = 0, stg2 = 2;
    for (int kt = 0; kt < NKT; ++kt) {
        if (kt == NKT - 1) cpa_wait<0>(); else cpa_wait<1>();
        __syncthreads();

        if (kt + 2 < NKT) issue_stage(kt + 2, stg2);

        const uint32_t xh = sb + stg * STG_B;
        const uint32_t wh = xh + TILE_X_B;

#pragma unroll
        for (int j = 0; j < 4; ++j) {
            uint32_t ah[4][4];
            const int aks = 2 * j + a_ks;
            const uint32_t axoff = (uint32_t)((aks ^ a_r7) << 4);
#pragma unroll
            for (int mi = 0; mi < 4; ++mi) {
                const uint32_t ro = (uint32_t)((a_row + mi * 16) * 128) + axoff;
                ldsm_x4(xh + ro, ah[mi][0], ah[mi][1], ah[mi][2], ah[mi][3]);
            }
            uint32_t bh[2][4];
            const int bks = 2 * j + b_ks;
            const uint32_t bxoff = (uint32_t)((bks ^ b_r7) << 4);
#pragma unroll
            for (int ni2 = 0; ni2 < 2; ++ni2) {
                const uint32_t ro = (uint32_t)((b_row + ni2 * 16) * 128) + bxoff;
                ldsm_x4(wh + ro, bh[ni2][0], bh[ni2][1], bh[ni2][2], bh[ni2][3]);
            }
#pragma unroll
            for (int mi = 0; mi < 4; ++mi) {
#pragma unroll
                for (int ni = 0; ni < 4; ++ni) {
                    const int g = ni >> 1, o = (ni & 1) * 2;
                    float* c = acc[mi][ni];
                    mma_fp16(c[0], c[1], c[2], c[3],
                             ah[mi][0], ah[mi][1], ah[mi][2], ah[mi][3],
                             bh[g][o], bh[g][o + 1]);
                }
            }
        }

        stg  = (stg  == 2) ? 0 : stg  + 1;
        stg2 = (stg2 == 2) ? 0 : stg2 + 1;
    }

    const int erow = lane >> 2;
    const int ecol = (lane & 3) * 2;
#pragma unroll
    for (int ni = 0; ni < 4; ++ni) {
        const int ncol = n0 + wn0 + ni * 8 + ecol;
        const float b0 = __ldg(&bias[ncol]);
        const float b1 = __ldg(&bias[ncol + 1]);
#pragma unroll
        for (int mi = 0; mi < 4; ++mi) {
            const int r0 = m0 + mi * 16 + erow;
            float2 v0 = { acc[mi][ni][0] + b0, acc[mi][ni][1] + b1 };
            float2 v1 = { acc[mi][ni][2] + b0, acc[mi][ni][3] + b1 };
            *(float2*)&out[(size_t)r0 * D_OUT + ncol] = v0;
            *(float2*)&out[(size_t)(r0 + 8) * D_OUT + ncol] = v1;
        }
    }
}

// ---------------------------------------------------------------------------
// Inputs (metadata order): x, W, b, lora_A, lora_B, expert_mask
// ---------------------------------------------------------------------------
extern "C" void kernel_launch(void* const* d_in, const int* in_sizes, int n_in,
                              void* d_out, int out_size)
{
    const float* x    = (const float*)d_in[0];
    const float* W    = (const float*)d_in[1];
    const float* b    = (const float*)d_in[2];
    const float* lA   = (const float*)d_in[3];
    const float* lB   = (const float*)d_in[4];
    const int*   mask = (const int*)d_in[5];
    float* out = (float*)d_out;

    static bool attr_done = false;
    if (!attr_done) {
        cudaFuncSetAttribute(gemm_mma_kernel,
                             cudaFuncAttributeMaxDynamicSharedMemorySize, SMEM_B);
        cudaFuncSetAttribute(fold_mma_kernel,
                             cudaFuncAttributeMaxDynamicSharedMemorySize, FSMEM_B);
        attr_done = true;
    }

    prep_kernel<<<NCONV + NAT + NBS, 256>>>(x, lA, lB, mask);
    dim3 grid_fold(D_IN / 128, D_OUT / 128);    // (16, 16)
    fold_mma_kernel<<<grid_fold, 256, FSMEM_B>>>(W);
    dim3 grid_gemm(D_OUT / 128, M_TOK / 64);    // (16, 128) = 2048 CTAs
    gemm_mma_kernel<<<grid_gemm, 128, SMEM_B>>>(b, out);
}

// round 12
// speedup vs baseline: 1.3813x; 1.0014x over previous
#include <cuda_runtime.h>
#include <cuda_fp16.h>
#include <cstdint>

#define D_IN   2048
#define D_OUT  2048
#define M_TOK  8192
#define RANK   16
#define NEXP   8
#define SCALING 1.0f

// fp16 operands, precomputed. Static device globals (no runtime alloc).
__device__ __half g_Xh[(size_t)M_TOK * D_IN];
__device__ __half g_Wh[(size_t)D_OUT * D_IN];
__device__ __half g_Bsh[(size_t)D_OUT * 128];   // [o][k=16e+r], masked
__device__ __half g_Ath[(size_t)D_IN * 128];    // [d][k]  (lora_A transposed)

// ---------------------------------------------------------------------------
// helpers
// ---------------------------------------------------------------------------
__device__ __forceinline__ uint32_t smem_u32(const void* p) {
    uint32_t a;
    asm("{ .reg .u64 t; cvta.to.shared.u64 t, %1; cvt.u32.u64 %0, t; }" : "=r"(a) : "l"(p));
    return a;
}
__device__ __forceinline__ void cpa16(uint32_t s, const void* g) {
    asm volatile("cp.async.cg.shared.global [%0], [%1], 16;" :: "r"(s), "l"(g));
}
__device__ __forceinline__ void cpa_commit() {
    asm volatile("cp.async.commit_group;" ::: "memory");
}
template <int N> __device__ __forceinline__ void cpa_wait() {
    asm volatile("cp.async.wait_group %0;" :: "n"(N) : "memory");
}
__device__ __forceinline__ void ldsm_x4(uint32_t addr, uint32_t& r0, uint32_t& r1,
                                        uint32_t& r2, uint32_t& r3) {
    asm volatile("ldmatrix.sync.aligned.m8n8.x4.shared.b16 {%0,%1,%2,%3}, [%4];"
                 : "=r"(r0), "=r"(r1), "=r"(r2), "=r"(r3) : "r"(addr));
}
__device__ __forceinline__ void mma_fp16(float& c0, float& c1, float& c2, float& c3,
                                         uint32_t a0, uint32_t a1, uint32_t a2, uint32_t a3,
                                         uint32_t b0, uint32_t b1) {
    asm volatile(
        "mma.sync.aligned.m16n8k16.row.col.f32.f16.f16.f32 "
        "{%0,%1,%2,%3}, {%4,%5,%6,%7}, {%8,%9}, {%0,%1,%2,%3};"
        : "+f"(c0), "+f"(c1), "+f"(c2), "+f"(c3)
        : "r"(a0), "r"(a1), "r"(a2), "r"(a3), "r"(b0), "r"(b1));
}
__device__ __forceinline__ uint2 pack_h4(float4 v) {
    __half2 p0 = __floats2half2_rn(v.x, v.y);
    __half2 p1 = __floats2half2_rn(v.z, v.w);
    uint2 u;
    u.x = *(uint32_t*)&p0;
    u.y = *(uint32_t*)&p1;
    return u;
}

// ---------------------------------------------------------------------------
// Kernel 0 (merged prep):
//  blocks [0, NCONV): convert x -> fp16 (2 float4/thread)
//  blocks [NCONV, NCONV+NAT): transpose lora_A -> Ath[d][k] fp16
//  blocks [NCONV+NAT, ...): build masked Bsh[o][k] fp16
// ---------------------------------------------------------------------------
#define NCONV ((M_TOK * D_IN / 8) / 256)   // 8192 blocks
#define NAT   128
#define NBS   64

__global__ __launch_bounds__(256) void prep_kernel(
    const float* __restrict__ x,
    const float* __restrict__ A,          // lora_A as [128, D_IN]
    const float* __restrict__ Bl,         // [E, D_OUT, R]
    const int* __restrict__ mask)
{
    const int t = threadIdx.x;
    const unsigned b = blockIdx.x;

    if (b < NCONV) {
        size_t i4 = (size_t)b * 512 + t;
        float4 v0 = __ldg((const float4*)x + i4);
        float4 v1 = __ldg((const float4*)x + i4 + 256);
        *(uint2*)&g_Xh[i4 * 4] = pack_h4(v0);
        *(uint2*)&g_Xh[(i4 + 256) * 4] = pack_h4(v1);
        return;
    }
    if (b < NCONV + NAT) {
        const int d0 = (int)(b - NCONV) * 16;
        const int k  = t >> 1;
        const int dg = (t & 1) * 8;
        float4 v0 = __ldg((const float4*)&A[(size_t)k * D_IN + d0 + dg]);
        float4 v1 = __ldg((const float4*)&A[(size_t)k * D_IN + d0 + dg + 4]);
        float vv[8] = {v0.x, v0.y, v0.z, v0.w, v1.x, v1.y, v1.z, v1.w};
#pragma unroll
        for (int j = 0; j < 8; ++j)
            g_Ath[(size_t)(d0 + dg + j) * 128 + k] = __float2half_rn(vv[j]);
        return;
    }
    {
        const int o = (int)(b - NCONV - NAT) * 32 + (t >> 3);
        const int e = t & 7;
        const float sc = (__ldg(&mask[e]) != 0) ? SCALING : 0.f;
        const float* src = &Bl[(size_t)e * D_OUT * RANK + (size_t)o * RANK];
#pragma unroll
        for (int h = 0; h < 2; ++h) {
            float4 v = __ldg((const float4*)(src + h * 8));
            float4 w = __ldg((const float4*)(src + h * 8 + 4));
            v.x *= sc; v.y *= sc; v.z *= sc; v.w *= sc;
            w.x *= sc; w.y *= sc; w.z *= sc; w.w *= sc;
            uint2 a = pack_h4(v), c = pack_h4(w);
            uint32_t* dst = (uint32_t*)&g_Bsh[(size_t)o * 128 + e * 16 + h * 8];
            dst[0] = a.x; dst[1] = a.y; dst[2] = c.x; dst[3] = c.y;
        }
    }
}

// ---------------------------------------------------------------------------
// Kernel 1: fold via tensor cores (proven round 10).
//   Weff[o,d] = W[o,d] + sum_{k<128} Bsh[o,k] * Ath[d,k]
// ---------------------------------------------------------------------------
#define FTILE_B 16384
#define FSTG_B  (2 * FTILE_B)
#define FSMEM_B (2 * FSTG_B)       // 64KB

__global__ __launch_bounds__(256, 2)
void fold_mma_kernel(const float* __restrict__ W)
{
    extern __shared__ __align__(1024) char smem[];
    const uint32_t sb = smem_u32(smem);

    const int t    = threadIdx.x;
    const int lane = t & 31;
    const int wid  = t >> 5;
    const int wm0  = (wid >> 2) * 64;
    const int wn0  = (wid & 3) * 32;
    const int d0   = blockIdx.x * 128;
    const int o0   = blockIdx.y * 128;

    const int a_row = wm0 + (lane & 7) + ((lane >> 3) & 1) * 8;
    const int a_ks  = (lane >> 4);
    const int b_row = wn0 + (lane & 7) + (lane >> 4) * 8;
    const int b_ks  = (lane >> 3) & 1;
    const int a_r7  = a_row & 7;
    const int b_r7  = b_row & 7;

    float acc[4][4][4];
#pragma unroll
    for (int i = 0; i < 4; ++i)
#pragma unroll
        for (int j = 0; j < 4; ++j)
#pragma unroll
            for (int q = 0; q < 4; ++q) acc[i][j][q] = 0.f;

#pragma unroll
    for (int s = 0; s < 2; ++s) {
        const uint32_t base = sb + s * FSTG_B;
        const int kbase = s * 64;
#pragma unroll
        for (int ii = 0; ii < 4; ++ii) {
            int c = t + ii * 256;
            int row = c >> 3, seg = c & 7;
            uint32_t soff = (uint32_t)(row * 128 + ((seg ^ (row & 7)) << 4));
            cpa16(base + soff, &g_Bsh[(size_t)(o0 + row) * 128 + kbase + seg * 8]);
            cpa16(base + FTILE_B + soff, &g_Ath[(size_t)(d0 + row) * 128 + kbase + seg * 8]);
        }
    }
    cpa_commit();
    cpa_wait<0>();
    __syncthreads();

#pragma unroll
    for (int s = 0; s < 2; ++s) {
        const uint32_t xh = sb + s * FSTG_B;
        const uint32_t wh = xh + FTILE_B;
#pragma unroll
        for (int j = 0; j < 4; ++j) {
            uint32_t ah[4][4];
            const int aks = 2 * j + a_ks;
            const uint32_t axoff = (uint32_t)((aks ^ a_r7) << 4);
#pragma unroll
            for (int mi = 0; mi < 4; ++mi) {
                const uint32_t ro = (uint32_t)((a_row + mi * 16) * 128) + axoff;
                ldsm_x4(xh + ro, ah[mi][0], ah[mi][1], ah[mi][2], ah[mi][3]);
            }
            uint32_t bh[2][4];
            const int bks = 2 * j + b_ks;
            const uint32_t bxoff = (uint32_t)((bks ^ b_r7) << 4);
#pragma unroll
            for (int ni2 = 0; ni2 < 2; ++ni2) {
                const uint32_t ro = (uint32_t)((b_row + ni2 * 16) * 128) + bxoff;
                ldsm_x4(wh + ro, bh[ni2][0], bh[ni2][1], bh[ni2][2], bh[ni2][3]);
            }
#pragma unroll
            for (int mi = 0; mi < 4; ++mi) {
#pragma unroll
                for (int ni = 0; ni < 4; ++ni) {
                    const int g = ni >> 1, o = (ni & 1) * 2;
                    float* c = acc[mi][ni];
                    mma_fp16(c[0], c[1], c[2], c[3],
                             ah[mi][0], ah[mi][1], ah[mi][2], ah[mi][3],
                             bh[g][o], bh[g][o + 1]);
                }
            }
        }
    }

    const int erow = lane >> 2;
    const int ecol = (lane & 3) * 2;
#pragma unroll
    for (int ni = 0; ni < 4; ++ni) {
        const int dcol = d0 + wn0 + ni * 8 + ecol;
#pragma unroll
        for (int mi = 0; mi < 4; ++mi) {
            const int orow = o0 + wm0 + mi * 16 + erow;
#pragma unroll
            for (int h = 0; h < 2; ++h) {
                const int r = orow + h * 8;
                float2 w = __ldg((const float2*)&W[(size_t)r * D_IN + dcol]);
                __half2 p = __floats2half2_rn(w.x + acc[mi][ni][h * 2 + 0],
                                              w.y + acc[mi][ni][h * 2 + 1]);
                *(uint32_t*)&g_Wh[(size_t)r * D_IN + dcol] = *(uint32_t*)&p;
            }
        }
    }
}

// ---------------------------------------------------------------------------
// Kernel 2: main fp16 GEMM. BM=64, BN=128, 128 threads (4 warps, warp 64x32),
// 3-stage cp.async + PER-J-STEP FRAGMENT DOUBLE BUFFERING: LDSM for step j+1
// issued before MMAs of step j, hiding shared-load latency under MMA issue.
// ---------------------------------------------------------------------------
#define BK 64
#define NKT (D_IN / BK)            // 32
#define TILE_X_B 8192              // X tile: 64 rows x 128B
#define TILE_W_B 16384             // W tile: 128 rows x 128B
#define STG_B  (TILE_X_B + TILE_W_B)   // 24KB per stage
#define NSTG   3
#define SMEM_B (NSTG * STG_B)      // 72KB

__global__ __launch_bounds__(128, 3)
void gemm_mma_kernel(const float* __restrict__ bias, float* __restrict__ out)
{
    extern __shared__ __align__(1024) char smem[];
    const uint32_t sb = smem_u32(smem);

    const int t    = threadIdx.x;
    const int lane = t & 31;
    const int wid  = t >> 5;               // 0..3
    const int wn0  = wid * 32;
    const int n0   = blockIdx.x * 128;
    const int m0   = blockIdx.y * 64;

    const int a_row = (lane & 7) + ((lane >> 3) & 1) * 8;        // + mi*16
    const int a_ks  = (lane >> 4);                               // + 2*j
    const int b_row = wn0 + (lane & 7) + (lane >> 4) * 8;        // + ni2*16
    const int b_ks  = (lane >> 3) & 1;                           // + 2*j
    const int a_r7  = a_row & 7;
    const int b_r7  = b_row & 7;

    float acc[4][4][4];
#pragma unroll
    for (int i = 0; i < 4; ++i)
#pragma unroll
        for (int j = 0; j < 4; ++j)
#pragma unroll
            for (int q = 0; q < 4; ++q) acc[i][j][q] = 0.f;

    auto issue_stage = [&](int kt, int stg) {
        const uint32_t base = sb + stg * STG_B;
        const int kbase = kt * BK;
#pragma unroll
        for (int ii = 0; ii < 4; ++ii) {
            int c = t + ii * 128;
            int row = c >> 3, seg = c & 7;
            uint32_t soff = (uint32_t)(row * 128 + ((seg ^ (row & 7)) << 4));
            cpa16(base + soff,
                  &g_Xh[(size_t)(m0 + row) * D_IN + kbase + seg * 8]);
        }
#pragma unroll
        for (int ii = 0; ii < 8; ++ii) {
            int c = t + ii * 128;
            int row = c >> 3, seg = c & 7;
            uint32_t soff = (uint32_t)(row * 128 + ((seg ^ (row & 7)) << 4));
            cpa16(base + TILE_X_B + soff,
                  &g_Wh[(size_t)(n0 + row) * D_IN + kbase + seg * 8]);
        }
        cpa_commit();
    };

    issue_stage(0, 0);
    issue_stage(1, 1);

    // double-buffered fragments
    uint32_t ah[2][4][4], bh[2][2][4];

    auto load_frags = [&](uint32_t xh, uint32_t wh, int j, int buf) {
        const int aks = 2 * j + a_ks;
        const uint32_t axoff = (uint32_t)((aks ^ a_r7) << 4);
#pragma unroll
        for (int mi = 0; mi < 4; ++mi) {
            const uint32_t ro = (uint32_t)((a_row + mi * 16) * 128) + axoff;
            ldsm_x4(xh + ro, ah[buf][mi][0], ah[buf][mi][1], ah[buf][mi][2], ah[buf][mi][3]);
        }
        const int bks = 2 * j + b_ks;
        const uint32_t bxoff = (uint32_t)((bks ^ b_r7) << 4);
#pragma unroll
        for (int ni2 = 0; ni2 < 2; ++ni2) {
            const uint32_t ro = (uint32_t)((b_row + ni2 * 16) * 128) + bxoff;
            ldsm_x4(wh + ro, bh[buf][ni2][0], bh[buf][ni2][1], bh[buf][ni2][2], bh[buf][ni2][3]);
        }
    };

    int stg = 0, stg2 = 2;
    for (int kt = 0; kt < NKT; ++kt) {
        if (kt == NKT - 1) cpa_wait<0>(); else cpa_wait<1>();
        __syncthreads();

        if (kt + 2 < NKT) issue_stage(kt + 2, stg2);

        const uint32_t xh = sb + stg * STG_B;
        const uint32_t wh = xh + TILE_X_B;

        load_frags(xh, wh, 0, 0);
#pragma unroll
        for (int j = 0; j < 4; ++j) {
            const int cur = j & 1;
            if (j < 3) load_frags(xh, wh, j + 1, cur ^ 1);
#pragma unroll
            for (int mi = 0; mi < 4; ++mi) {
#pragma unroll
                for (int ni = 0; ni < 4; ++ni) {
                    const int g = ni >> 1, o = (ni & 1) * 2;
                    float* c = acc[mi][ni];
                    mma_fp16(c[0], c[1], c[2], c[3],
                             ah[cur][mi][0], ah[cur][mi][1], ah[cur][mi][2], ah[cur][mi][3],
                             bh[cur][g][o], bh[cur][g][o + 1]);
                }
            }
        }

        stg  = (stg  == 2) ? 0 : stg  + 1;
        stg2 = (stg2 == 2) ? 0 : stg2 + 1;
    }

    const int erow = lane >> 2;
    const int ecol = (lane & 3) * 2;
#pragma unroll
    for (int ni = 0; ni < 4; ++ni) {
        const int ncol = n0 + wn0 + ni * 8 + ecol;
        const float b0 = __ldg(&bias[ncol]);
        const float b1 = __ldg(&bias[ncol + 1]);
#pragma unroll
        for (int mi = 0; mi < 4; ++mi) {
            const int r0 = m0 + mi * 16 + erow;
            float2 v0 = { acc[mi][ni][0] + b0, acc[mi][ni][1] + b1 };
            float2 v1 = { acc[mi][ni][2] + b0, acc[mi][ni][3] + b1 };
            *(float2*)&out[(size_t)r0 * D_OUT + ncol] = v0;
            *(float2*)&out[(size_t)(r0 + 8) * D_OUT + ncol] = v1;
        }
    }
}

// ---------------------------------------------------------------------------
// Inputs (metadata order): x, W, b, lora_A, lora_B, expert_mask
// ---------------------------------------------------------------------------
extern "C" void kernel_launch(void* const* d_in, const int* in_sizes, int n_in,
                              void* d_out, int out_size)
{
    const float* x    = (const float*)d_in[0];
    const float* W    = (const float*)d_in[1];
    const float* b    = (const float*)d_in[2];
    const float* lA   = (const float*)d_in[3];
    const float* lB   = (const float*)d_in[4];
    const int*   mask = (const int*)d_in[5];
    float* out = (float*)d_out;

    static bool attr_done = false;
    if (!attr_done) {
        cudaFuncSetAttribute(gemm_mma_kernel,
                             cudaFuncAttributeMaxDynamicSharedMemorySize, SMEM_B);
        cudaFuncSetAttribute(fold_mma_kernel,
                             cudaFuncAttributeMaxDynamicSharedMemorySize, FSMEM_B);
        attr_done = true;
    }

    prep_kernel<<<NCONV + NAT + NBS, 256>>>(x, lA, lB, mask);
    dim3 grid_fold(D_IN / 128, D_OUT / 128);    // (16, 16)
    fold_mma_kernel<<<grid_fold, 256, FSMEM_B>>>(W);
    dim3 grid_gemm(D_OUT / 128, M_TOK / 64);    // (16, 128) = 2048 CTAs
    gemm_mma_kernel<<<grid_gemm, 128, SMEM_B>>>(b, out);
}